// round 5
// baseline (speedup 1.0000x reference)
#include <cuda_runtime.h>
#include <cstdint>

// PointerNet_30949534335591
//
// Mathematical reduction (verified R2/R4: passed, rel_err = 0.0):
// ptr_W has shape (1, H), so logits = h @ ptr_W.T + ptr_b is [B, 1];
// argmax over axis=1 of a single-column tensor is identically 0 for
// every row and every of the S decoder steps ("always 0, faithful to
// source"). Output ptrs.T is a constant zeros tensor [256, 512],
// independent of all 11 inputs; both LSTM scans are dead code.
//
// Lever history:
//   R2 kernel (128x256, 1 STG.128/thread):      5.0 us  <- best
//   R4 cudaMemsetAsync (graph memset node):     6.0 us  REGRESSION
//     -> captured memset replays slower than a user kernel node for
//        tiny fills; memset lever is dead.
// R5: revert to kernel node, trimmed: 64 CTAs x 256 thr, 2 independent
// STG.128 per thread (MLP=2), no tail code, 2 params. All remaining
// time is launch + graph-replay overhead; stores are ~80 cyc of L2.

__global__ void __launch_bounds__(256, 1)
pointer_net_zero_kernel(int4* __restrict__ out4, int n4) {
    int i = (blockIdx.x * blockDim.x + threadIdx.x) * 2;
    const int4 z = make_int4(0, 0, 0, 0);
    if (i < n4) {
        out4[i] = z;
        if (i + 1 < n4) out4[i + 1] = z;
    }
}

extern "C" void kernel_launch(void* const* d_in, const int* in_sizes, int n_in,
                              void* d_out, int out_size) {
    (void)d_in; (void)in_sizes; (void)n_in;
    const int threads = 256;
    int n4 = out_size >> 2;                            // 32768 int4 chunks
    int blocks = (n4 / 2 + threads - 1) / threads;     // 64 CTAs
    if (blocks < 1) blocks = 1;
    pointer_net_zero_kernel<<<blocks, threads>>>((int4*)d_out, n4);
}

// round 6
// speedup vs baseline: 1.0678x; 1.0678x over previous
#include <cuda_runtime.h>
#include <cstdint>

// PointerNet_30949534335591
//
// Mathematical reduction (verified R2/R4/R5: passed, rel_err = 0.0):
// ptr_W has shape (1, H), so logits = h @ ptr_W.T + ptr_b is [B, 1];
// argmax over axis=1 of a single-column tensor is identically 0 for
// every row and every decoder step ("always 0, faithful to source").
// Output ptrs.T is a constant zeros tensor [256, 512], independent of
// all 11 inputs; both LSTM scans are dead code. Only required work:
// un-poison d_out with 512 KB of zero stores.
//
// Lever history:
//   R2 kernel 128x256, 1 STG.128/thr (+dead tail): 5.02 us  <- best
//   R4 cudaMemsetAsync (graph memset node):        6.02 us  regression
//   R5 64x256, 2 dependent STG.128/thr:            6.05 us  regression
//     (ncu kernel 3.62 -> 4.13 us; fewer CTAs didn't help, extra
//      per-thread work + index mul hurt; ~0.5-1 us run noise observed)
// R6: revert to the exact R2 launch shape (128 CTAs x 256 threads, one
// predicated STG.E.128 per thread), minus R2's dead tail loop and
// unused params. This is the measured-fastest shape with strictly
// fewer instructions. Remaining time is graph-replay + launch floor.

__global__ void __launch_bounds__(256, 1)
pointer_net_zero_kernel(int4* __restrict__ out4, int n4) {
    int i = blockIdx.x * blockDim.x + threadIdx.x;
    if (i < n4) {
        out4[i] = make_int4(0, 0, 0, 0);
    }
}

extern "C" void kernel_launch(void* const* d_in, const int* in_sizes, int n_in,
                              void* d_out, int out_size) {
    (void)d_in; (void)in_sizes; (void)n_in;
    const int threads = 256;
    int n4 = out_size >> 2;                          // 32768 int4 chunks
    int blocks = (n4 + threads - 1) / threads;       // 128 CTAs
    if (blocks < 1) blocks = 1;
    pointer_net_zero_kernel<<<blocks, threads>>>((int4*)d_out, n4);
}

// round 8
// speedup vs baseline: 1.2038x; 1.1274x over previous
#include <cuda_runtime.h>
#include <cstdint>

// PointerNet_30949534335591
//
// Mathematical reduction (verified R2/R4/R5/R6: passed, rel_err = 0.0):
// ptr_W has shape (1, H), so logits = h @ ptr_W.T + ptr_b is [B, 1];
// argmax over axis=1 of a single-column tensor is identically 0 for
// every row and every decoder step ("always 0, faithful to source").
// Output ptrs.T is a constant zeros tensor [256, 512], independent of
// all 11 inputs; both LSTM scans are dead code. Only required work:
// un-poison d_out with 512 KB of zero stores.
//
// Lever history:
//   R2 128x256, 1 STG.128/thr:        5.02 us total / 3.62 us kernel
//   R4 cudaMemsetAsync node:          6.02 us  (memset lever dead)
//   R5 64x256, 2 dep STG.128/thr:     6.05 us / 4.13 us  (regression)
//   R6 = R2 shape, trimmed:           5.66 us / 3.90 us
//     -> same shape as R2 spread 0.5 us: noise floor ~ +/-0.5 us;
//        kernel is launch/ramp-bound (L2 1.4%, issue 3.2%).
//   R7 256-bit stores: broker container failure (same flake as
//     R0/R1/R3, where identical kernels later passed) — never ran.
// R8: retry R7 unchanged. 16384 threads (128 CTAs x 128), exactly one
// STG.256 (st.global.v8.b32, Blackwell) per thread — halves warp count
// and L1tex wavefronts vs R2. If flat vs R6, converged at harness
// floor (~5.3 +/- 0.5 us) and the session is done.

__global__ void __launch_bounds__(128, 1)
pointer_net_zero_kernel(char* __restrict__ out, int n32) {
    int i = blockIdx.x * blockDim.x + threadIdx.x;
    if (i < n32) {
        // one 32-byte store per thread (sm_100a 256-bit store)
        asm volatile(
            "st.global.v8.b32 [%0], {%1, %1, %1, %1, %1, %1, %1, %1};"
            :: "l"(out + (size_t)i * 32), "r"(0) : "memory");
    }
}

extern "C" void kernel_launch(void* const* d_in, const int* in_sizes, int n_in,
                              void* d_out, int out_size) {
    (void)d_in; (void)in_sizes; (void)n_in;
    const int threads = 128;
    int bytes = out_size * 4;                        // int32 output
    int n32 = bytes >> 5;                            // 16384 32B chunks
    int blocks = (n32 + threads - 1) / threads;      // 128 CTAs
    if (blocks < 1) blocks = 1;
    pointer_net_zero_kernel<<<blocks, threads>>>((char*)d_out, n32);
}

// round 9
// speedup vs baseline: 1.2115x; 1.0064x over previous
#include <cuda_runtime.h>
#include <cstdint>

// PointerNet_30949534335591 — FINAL
//
// Mathematical reduction (verified bit-exact in R2/R4/R5/R6/R8):
// ptr_W has shape (1, H), so logits = h @ ptr_W.T + ptr_b is [B, 1];
// argmax over axis=1 of a single-column tensor is identically 0 for
// every row and every decoder step ("always 0, faithful to source").
// Output ptrs.T is a constant zeros tensor [256, 512], independent of
// all 11 inputs; both LSTM scans (1024 sequential GEMM steps) are dead
// code w.r.t. the observable output. Only required work: un-poison
// d_out with 512 KB of zero stores.
//
// Lever history (total us / ncu kernel us):
//   R2 128x256, 1 STG.128/thr:     5.02 / 3.62
//   R4 cudaMemsetAsync node:       6.02 /  —    memset node slower
//   R5 64x256, 2 STG.128/thr:      6.05 / 4.13  regression
//   R6 = R2 trimmed:               5.66 / 3.90  (same shape as R2:
//                                                noise ~ +/-0.5 us)
//   R8 128x128, 1 STG.256/thr:     5.02 / 3.58  <- best, final
//
// Conclusion: launch/replay-floor bound (L2 1.5%, issue 1.6%, DRAM 0%).
// One kernel node, one predicated 256-bit store per thread, single
// wave, 512 warps — minimum expressible work. Converged.

__global__ void __launch_bounds__(128, 1)
pointer_net_zero_kernel(char* __restrict__ out, int n32) {
    int i = blockIdx.x * blockDim.x + threadIdx.x;
    if (i < n32) {
        // one 32-byte store per thread (sm_100a 256-bit store)
        asm volatile(
            "st.global.v8.b32 [%0], {%1, %1, %1, %1, %1, %1, %1, %1};"
            :: "l"(out + (size_t)i * 32), "r"(0) : "memory");
    }
}

extern "C" void kernel_launch(void* const* d_in, const int* in_sizes, int n_in,
                              void* d_out, int out_size) {
    (void)d_in; (void)in_sizes; (void)n_in;
    const int threads = 128;
    int bytes = out_size * 4;                        // int32 output
    int n32 = bytes >> 5;                            // 16384 32B chunks
    int blocks = (n32 + threads - 1) / threads;      // 128 CTAs
    if (blocks < 1) blocks = 1;
    pointer_net_zero_kernel<<<blocks, threads>>>((char*)d_out, n32);
}